// round 5
// baseline (speedup 1.0000x reference)
#include <cuda_runtime.h>
#include <math.h>

// Problem dims
#define Bq   32
#define Sq   256
#define Iq   128
#define Hq   512
#define Cq   64
#define BUFD 17
#define OUTL 64

#define NCTA 128
#define NTHR 256
#define SHS  516   // padded smem row stride (floats): conflict-free LDS.128

// ---------------- device globals (no runtime allocation allowed) ----------------
__device__ __align__(16) float g_WAh[Hq * 1024];     // rows k<512 of [W_in | W_in@W_pass], col-interleaved (2c=h1, 2c+1=p)
__device__ __align__(16) float g_WCx[Iq * 1024];     // rows 512..639, same interleave (x part)
__device__ __align__(16) float g_WB [Hq * 1024];     // [W_tau | W_mem] col-interleaved
__device__ __align__(16) float g_WD [Hq * 576];      // decode: cols 0..511 = W_comb_h, 512..575 = W_out
__device__ __align__(16) float g_bA [1024];
__device__ __align__(16) float g_bB [1024];
__device__ __align__(16) float g_bD [576];
__device__ __align__(16) float g_XW [Sq * Bq * 1024]; // x @ [Wi_x | Wi_x Wp], layout [(b*256+s)][1024]
__device__ __align__(16) float g_hbuf[Bq * Hq];       // per-step h
__device__ __align__(16) float g_dbuf[BUFD * Bq * Hq];// delay buffer, [d][b][h]
__device__ unsigned g_tickets;                        // monotonic barrier tickets

// ---------------- precompute kernels ----------------

// W_comb[k][c] = sum_j W_in[k][j] * W_pass[j][c]; build interleaved WAh/WCx and WD h-part.
__global__ void k_comb(const float* __restrict__ W_in, const float* __restrict__ W_pass) {
    int id = blockIdx.x * blockDim.x + threadIdx.x;  // 160*128 = 20480
    int kq = id >> 7;        // 0..159 (k quad)
    int cq = id & 127;       // 0..127 (col quad)
    float acc[4][4];
#pragma unroll
    for (int u = 0; u < 4; ++u)
#pragma unroll
        for (int v = 0; v < 4; ++v) acc[u][v] = 0.f;

    for (int j = 0; j < Hq; ++j) {
        float4 w = __ldg((const float4*)(W_pass + j * Hq + cq * 4));
#pragma unroll
        for (int u = 0; u < 4; ++u) {
            float a = __ldg(W_in + (kq * 4 + u) * Hq + j);
            acc[u][0] = fmaf(a, w.x, acc[u][0]);
            acc[u][1] = fmaf(a, w.y, acc[u][1]);
            acc[u][2] = fmaf(a, w.z, acc[u][2]);
            acc[u][3] = fmaf(a, w.w, acc[u][3]);
        }
    }
#pragma unroll
    for (int u = 0; u < 4; ++u) {
        int k = kq * 4 + u;
        if (k < Hq) {
            int base = k * 1024;
#pragma unroll
            for (int v = 0; v < 4; ++v) {
                int c = cq * 4 + v;
                g_WAh[base + 2 * c]     = W_in[k * Hq + c];
                g_WAh[base + 2 * c + 1] = acc[u][v];
            }
            float4 o = make_float4(acc[u][0], acc[u][1], acc[u][2], acc[u][3]);
            *(float4*)(g_WD + k * 576 + cq * 4) = o;
        } else {
            int i = k - Hq;
            int base = i * 1024;
#pragma unroll
            for (int v = 0; v < 4; ++v) {
                int c = cq * 4 + v;
                g_WCx[base + 2 * c]     = W_in[k * Hq + c];
                g_WCx[base + 2 * c + 1] = acc[u][v];
            }
        }
    }
}

// interleave W_tau / W_mem into g_WB; copy W_out into g_WD cols 512..575
__global__ void k_wb(const float* __restrict__ W_tau, const float* __restrict__ W_mem,
                     const float* __restrict__ W_out) {
    int id = blockIdx.x * blockDim.x + threadIdx.x;  // 262144
    int k = id >> 9, c = id & 511;
    g_WB[k * 1024 + 2 * c]     = W_tau[k * Hq + c];
    g_WB[k * 1024 + 2 * c + 1] = W_mem[k * Hq + c];
    if (id < Hq * Cq) {
        int k2 = id >> 6, c2 = id & 63;
        g_WD[k2 * 576 + 512 + c2] = W_out[k2 * Cq + c2];
    }
}

// biases: bc = b_in @ W_pass + b_pass; assemble bA/bB/bD
__global__ void k_bias(const float* __restrict__ b_in, const float* __restrict__ W_pass,
                       const float* __restrict__ b_pass, const float* __restrict__ b_tau,
                       const float* __restrict__ b_mem, const float* __restrict__ b_out) {
    int c = threadIdx.x;  // 512 threads, 1 block
    float acc = b_pass[c];
    for (int j = 0; j < Hq; ++j) acc = fmaf(b_in[j], W_pass[j * Hq + c], acc);
    g_bA[2 * c]     = b_in[c];
    g_bA[2 * c + 1] = acc;
    g_bD[c]         = acc;
    g_bB[2 * c]     = b_tau[c];
    g_bB[2 * c + 1] = b_mem[c];
    if (c < Cq) g_bD[512 + c] = b_out[c];
}

__global__ void k_zero() {
    int id = blockIdx.x * blockDim.x + threadIdx.x;
    if (id < (BUFD * Bq * Hq) / 4) ((float4*)g_dbuf)[id] = make_float4(0.f, 0.f, 0.f, 0.f);
}

// XW[(sb)][col] = sum_i x[sb][i] * WCx[i][col],  sb = b*256+s (x is [B][S][I] contiguous)
__global__ void k_xw(const float* __restrict__ x) {
    __shared__ float sh_x[64 * 129];
    int tid = threadIdx.x;
    int sb0 = blockIdx.x * 64;   // 128 blocks in x
    int cq0 = blockIdx.y * 4;    // 64 blocks in y
    for (int idx = tid; idx < 64 * 128; idx += NTHR) {
        int sl = idx >> 7, i = idx & 127;
        sh_x[sl * 129 + i] = x[(sb0 + sl) * Iq + i];
    }
    __syncthreads();
    int cql = tid >> 6, sl = tid & 63;
    int cq = cq0 + cql;
    float4 acc = make_float4(0.f, 0.f, 0.f, 0.f);
#pragma unroll 4
    for (int i = 0; i < Iq; ++i) {
        float a = sh_x[sl * 129 + i];
        float4 w = __ldg((const float4*)(g_WCx + i * 1024 + cq * 4));
        acc.x = fmaf(a, w.x, acc.x);
        acc.y = fmaf(a, w.y, acc.y);
        acc.z = fmaf(a, w.z, acc.z);
        acc.w = fmaf(a, w.w, acc.w);
    }
    *(float4*)(g_XW + (sb0 + sl) * 1024 + cq * 4) = acc;
}

// ---------------- persistent RNN kernel ----------------

__device__ __forceinline__ void grid_barrier() {
    __syncthreads();
    __threadfence();
    if (threadIdx.x == 0) {
        unsigned t = atomicAdd(&g_tickets, 1u);
        unsigned target = (t - (t % NCTA)) + NCTA;   // NCTA divides 2^32 -> wrap-safe
        volatile unsigned* p = &g_tickets;
        while ((int)(*p - target) < 0) __nanosleep(64);
    }
    __syncthreads();
}

// stage a 32x512 activation matrix (contiguous in gmem) into padded smem
__device__ __forceinline__ void stage_load(float* sh_in, const float* __restrict__ src) {
    int tid = threadIdx.x;
#pragma unroll
    for (int i = tid; i < Bq * (Hq / 4); i += NTHR) {
        int b = i >> 7, h4 = i & 127;
        float4 v = __ldcg((const float4*)(src + b * Hq + h4 * 4));
        *(float4*)(sh_in + b * SHS + h4 * 4) = v;
    }
}

// compute 32 rows x 8 stored cols, K=512 from sh_in; result in sh_out[32][8]
__device__ __forceinline__ void gemm8(const float* __restrict__ W, int wstride,
                                      const float* __restrict__ bias, int colbase,
                                      const float* sh_in, float* sh_red, float* sh_out) {
    int tid = threadIdx.x;
    int r = tid & 31, kc = (tid >> 5) & 3, q = tid >> 7;  // row, K-chunk, col-quad
    const float* wp = W + (kc * 128) * wstride + colbase + q * 4;
    const float* ap = sh_in + r * SHS + kc * 128;
    float4 acc = make_float4(0.f, 0.f, 0.f, 0.f);
#pragma unroll 4
    for (int k = 0; k < 128; k += 4) {
        float4 a  = *(const float4*)(ap + k);
        float4 w0 = __ldg((const float4*)(wp + (k + 0) * wstride));
        float4 w1 = __ldg((const float4*)(wp + (k + 1) * wstride));
        float4 w2 = __ldg((const float4*)(wp + (k + 2) * wstride));
        float4 w3 = __ldg((const float4*)(wp + (k + 3) * wstride));
        acc.x = fmaf(a.x, w0.x, acc.x); acc.y = fmaf(a.x, w0.y, acc.y);
        acc.z = fmaf(a.x, w0.z, acc.z); acc.w = fmaf(a.x, w0.w, acc.w);
        acc.x = fmaf(a.y, w1.x, acc.x); acc.y = fmaf(a.y, w1.y, acc.y);
        acc.z = fmaf(a.y, w1.z, acc.z); acc.w = fmaf(a.y, w1.w, acc.w);
        acc.x = fmaf(a.z, w2.x, acc.x); acc.y = fmaf(a.z, w2.y, acc.y);
        acc.z = fmaf(a.z, w2.z, acc.z); acc.w = fmaf(a.z, w2.w, acc.w);
        acc.x = fmaf(a.w, w3.x, acc.x); acc.y = fmaf(a.w, w3.y, acc.y);
        acc.z = fmaf(a.w, w3.z, acc.z); acc.w = fmaf(a.w, w3.w, acc.w);
    }
    ((float4*)sh_red)[(q * 4 + kc) * 32 + r] = acc;
    __syncthreads();
    if (tid < 64) {
        int rr = tid & 31, qq = tid >> 5;
        float4 s0 = ((float4*)sh_red)[(qq * 4 + 0) * 32 + rr];
        float4 s1 = ((float4*)sh_red)[(qq * 4 + 1) * 32 + rr];
        float4 s2 = ((float4*)sh_red)[(qq * 4 + 2) * 32 + rr];
        float4 s3 = ((float4*)sh_red)[(qq * 4 + 3) * 32 + rr];
        float4 bb = *(const float4*)(bias + colbase + qq * 4);
        float4 o;
        o.x = s0.x + s1.x + s2.x + s3.x + bb.x;
        o.y = s0.y + s1.y + s2.y + s3.y + bb.y;
        o.z = s0.z + s1.z + s2.z + s3.z + bb.z;
        o.w = s0.w + s1.w + s2.w + s3.w + bb.w;
        *(float4*)(sh_out + rr * 8 + qq * 4) = o;
    }
    __syncthreads();
}

// sigmoid gates + delay-buffer shift for this CTA's 4 h-cols
__device__ __forceinline__ void buf_update(int cta, const float* sh_in, const float* sh_out) {
    int tid = threadIdx.x;
    if (tid < 128) {
        int b = tid >> 2, hc = tid & 3;
        int col = cta * 4 + hc;
        float ta = sh_out[b * 8 + 2 * hc];
        float me = sh_out[b * 8 + 2 * hc + 1];
        float tau = 16.f / (1.f + expf(-ta));
        tau = fminf(fmaxf(tau, 1.f), 16.f);
        float mem = 1.f / (1.f + expf(-me));
        float hv = sh_in[b * SHS + col];
        int base = b * Hq + col;
#pragma unroll
        for (int d = 0; d < 16; ++d) {
            float nxt = __ldcg(g_dbuf + (d + 1) * (Bq * Hq) + base);
            float w = mem / (1.f + fabsf(tau - (float)(d + 1)));
            __stcg(g_dbuf + d * (Bq * Hq) + base, fmaf(w, hv, nxt));
        }
        __stcg(g_dbuf + 16 * (Bq * Hq) + base, 0.f);
    }
}

__global__ void __launch_bounds__(NTHR, 1) k_rnn(const int* __restrict__ lengths,
                                                 float* __restrict__ out) {
    extern __shared__ float sm[];
    float* sh_in  = sm;                  // 32 * 516
    float* sh_red = sm + Bq * SHS;       // 256 * 4
    float* sh_out = sh_red + 1024;       // 32 * 8
    int tid = threadIdx.x, cta = blockIdx.x;

    // ---- encode: 256 steps ----
    for (int t = 0; t < Sq; ++t) {
        // stage A: h0 @ [W_in | W_comb] + XW_t ; combine with mask -> h
        stage_load(sh_in, g_dbuf);  // plane 0 = h0
        __syncthreads();
        gemm8(g_WAh, 1024, g_bA, cta * 8, sh_in, sh_red, sh_out);
        if (tid < 128) {
            int b = tid >> 2, hc = tid & 3;
            int col = cta * 4 + hc;
            float2 xw = *(const float2*)(g_XW + (b * Sq + t) * 1024 + cta * 8 + 2 * hc);
            float h1 = sh_out[b * 8 + 2 * hc]     + xw.x;
            float p  = sh_out[b * 8 + 2 * hc + 1] + xw.y;
            float h = (t < lengths[b]) ? p : h1;
            __stcg(g_hbuf + b * Hq + col, h);
        }
        grid_barrier();
        // stage B: h @ [W_tau | W_mem] -> gates; buffer shift
        stage_load(sh_in, g_hbuf);
        __syncthreads();
        gemm8(g_WB, 1024, g_bB, cta * 8, sh_in, sh_red, sh_out);
        buf_update(cta, sh_in, sh_out);
        grid_barrier();
    }

    // ---- decode: 64 steps ----
    for (int t = 0; t < OUTL; ++t) {
        if (cta < 72) {   // 72*8 = 576 cols: 512 h cols + 64 out cols
            stage_load(sh_in, g_dbuf);  // plane 0 = h0
            __syncthreads();
            gemm8(g_WD, 576, g_bD, cta * 8, sh_in, sh_red, sh_out);
            {
                int b = tid >> 3, j = tid & 7;
                int sc = cta * 8 + j;
                float v = sh_out[b * 8 + j];
                if (sc < Hq) __stcg(g_hbuf + b * Hq + sc, v);
                else          out[b * (OUTL * Cq) + t * Cq + (sc - 512)] = v;
            }
        }
        grid_barrier();
        stage_load(sh_in, g_hbuf);
        __syncthreads();
        gemm8(g_WB, 1024, g_bB, cta * 8, sh_in, sh_red, sh_out);
        buf_update(cta, sh_in, sh_out);
        grid_barrier();
    }
}

// ---------------- launch ----------------
extern "C" void kernel_launch(void* const* d_in, const int* in_sizes, int n_in,
                              void* d_out, int out_size) {
    const float* x       = (const float*)d_in[0];
    const int*   lengths = (const int*)d_in[1];
    int wi = 2;
    if (n_in >= 13 && in_sizes[2] == 1) wi = 3;  // skip scalar out_lengths if materialized
    const float* W_in   = (const float*)d_in[wi + 0];
    const float* b_in   = (const float*)d_in[wi + 1];
    const float* W_pass = (const float*)d_in[wi + 2];
    const float* b_pass = (const float*)d_in[wi + 3];
    const float* W_tau  = (const float*)d_in[wi + 4];
    const float* b_tau  = (const float*)d_in[wi + 5];
    const float* W_mem  = (const float*)d_in[wi + 6];
    const float* b_mem  = (const float*)d_in[wi + 7];
    const float* W_out  = (const float*)d_in[wi + 8];
    const float* b_out  = (const float*)d_in[wi + 9];
    float* out = (float*)d_out;

    static int smem_set = 0;
    const int smem_bytes = (Bq * SHS + 1024 + Bq * 8) * (int)sizeof(float);  // 71168
    if (!smem_set) {
        cudaFuncSetAttribute(k_rnn, cudaFuncAttributeMaxDynamicSharedMemorySize, smem_bytes);
        smem_set = 1;
    }

    k_zero<<<272, 256>>>();
    k_comb<<<80, 256>>>(W_in, W_pass);
    k_wb<<<1024, 256>>>(W_tau, W_mem, W_out);
    k_bias<<<1, 512>>>(b_in, W_pass, b_pass, b_tau, b_mem, b_out);
    k_xw<<<dim3(128, 64), 256>>>(x);
    k_rnn<<<NCTA, NTHR, smem_bytes>>>(lengths, out);
}

// round 8
// speedup vs baseline: 1.1908x; 1.1908x over previous
#include <cuda_runtime.h>
#include <math.h>

// Problem dims
#define Bq   32
#define Sq   256
#define Iq   128
#define Hq   512
#define Cq   64
#define BUFD 17
#define OUTL 64

#define NCTA 128
#define NTHR 256
#define SHS  516   // padded smem row stride (floats): conflict-free LDS.128

// ---------------- device globals (no runtime allocation allowed) ----------------
__device__ __align__(16) float g_WAh[Hq * 1024];     // rows k<512 of [W_in | W_in@W_pass], col-interleaved (2c=h1, 2c+1=p)
__device__ __align__(16) float g_WCx[Iq * 1024];     // rows 512..639, same interleave (x part)
__device__ __align__(16) float g_WB [Hq * 1024];     // [W_tau | W_mem] col-interleaved
__device__ __align__(16) float g_WD [Hq * 576];      // decode: cols 0..511 = W_comb_h, 512..575 = W_out
__device__ __align__(16) float g_bA [1024];
__device__ __align__(16) float g_bB [1024];
__device__ __align__(16) float g_bD [576];
__device__ __align__(16) float g_XW [Sq * Bq * 1024]; // x @ [Wi_x | Wi_x Wp], layout [(b*256+s)][1024]
__device__ __align__(16) float g_hbuf[Bq * Hq];       // per-step h
__device__ __align__(16) float g_dbuf[BUFD * Bq * Hq];// delay buffer, [d][b][h]
__device__ unsigned g_tickets;                        // monotonic barrier tickets (reset each call by k_pre)

// ---------------- fused precompute kernel ----------------
// grid = 1121 blocks x 256 threads; role dispatch by blockIdx.x:
//   [0,80)      : W_comb + interleave WAh/WCx + WD h-part
//   [80,1104)   : interleave WB, copy W_out into WD
//   1104        : biases
//   [1105,1121) : zero dbuf, reset tickets
__global__ void k_pre(const float* __restrict__ W_in, const float* __restrict__ W_pass,
                      const float* __restrict__ W_tau, const float* __restrict__ W_mem,
                      const float* __restrict__ W_out,
                      const float* __restrict__ b_in, const float* __restrict__ b_pass,
                      const float* __restrict__ b_tau, const float* __restrict__ b_mem,
                      const float* __restrict__ b_out) {
    int blk = blockIdx.x, tid = threadIdx.x;
    if (blk < 80) {
        // ---- comb role ----
        int id = blk * 256 + tid;     // 0..20479
        int kq = id >> 7;             // 0..159
        int cq = id & 127;            // 0..127
        float acc[4][4];
#pragma unroll
        for (int u = 0; u < 4; ++u)
#pragma unroll
            for (int v = 0; v < 4; ++v) acc[u][v] = 0.f;
        for (int j = 0; j < Hq; ++j) {
            float4 w = __ldg((const float4*)(W_pass + j * Hq + cq * 4));
#pragma unroll
            for (int u = 0; u < 4; ++u) {
                float a = __ldg(W_in + (kq * 4 + u) * Hq + j);
                acc[u][0] = fmaf(a, w.x, acc[u][0]);
                acc[u][1] = fmaf(a, w.y, acc[u][1]);
                acc[u][2] = fmaf(a, w.z, acc[u][2]);
                acc[u][3] = fmaf(a, w.w, acc[u][3]);
            }
        }
#pragma unroll
        for (int u = 0; u < 4; ++u) {
            int k = kq * 4 + u;
            if (k < Hq) {
                int base = k * 1024;
#pragma unroll
                for (int v = 0; v < 4; ++v) {
                    int c = cq * 4 + v;
                    g_WAh[base + 2 * c]     = W_in[k * Hq + c];
                    g_WAh[base + 2 * c + 1] = acc[u][v];
                }
                float4 o = make_float4(acc[u][0], acc[u][1], acc[u][2], acc[u][3]);
                *(float4*)(g_WD + k * 576 + cq * 4) = o;
            } else {
                int i = k - Hq;
                int base = i * 1024;
#pragma unroll
                for (int v = 0; v < 4; ++v) {
                    int c = cq * 4 + v;
                    g_WCx[base + 2 * c]     = W_in[k * Hq + c];
                    g_WCx[base + 2 * c + 1] = acc[u][v];
                }
            }
        }
    } else if (blk < 1104) {
        // ---- WB interleave + W_out copy ----
        int id = (blk - 80) * 256 + tid;  // 0..262143
        int k = id >> 9, c = id & 511;
        g_WB[k * 1024 + 2 * c]     = W_tau[k * Hq + c];
        g_WB[k * 1024 + 2 * c + 1] = W_mem[k * Hq + c];
        if (id < Hq * Cq) {
            int k2 = id >> 6, c2 = id & 63;
            g_WD[k2 * 576 + 512 + c2] = W_out[k2 * Cq + c2];
        }
    } else if (blk == 1104) {
        // ---- bias role: c = tid and tid+256 ----
#pragma unroll
        for (int h = 0; h < 2; ++h) {
            int c = tid + h * 256;
            float acc = b_pass[c];
            for (int j = 0; j < Hq; ++j) acc = fmaf(b_in[j], W_pass[j * Hq + c], acc);
            g_bA[2 * c]     = b_in[c];
            g_bA[2 * c + 1] = acc;
            g_bD[c]         = acc;
            g_bB[2 * c]     = b_tau[c];
            g_bB[2 * c + 1] = b_mem[c];
            if (c < Cq) g_bD[512 + c] = b_out[c];
        }
    } else {
        // ---- zero dbuf (16 blocks x 256 threads x 17 float4) + reset tickets ----
        int id = (blk - 1105) * 256 + tid;      // 0..4095
        float4 z = make_float4(0.f, 0.f, 0.f, 0.f);
#pragma unroll
        for (int d = 0; d < BUFD; ++d)
            ((float4*)g_dbuf)[d * 4096 + id] = z;
        if (blk == 1105 && tid == 0) g_tickets = 0u;
    }
}

// XW[(sb)][col] = sum_i x[sb][i] * WCx[i][col],  sb = b*256+s (x is [B][S][I] contiguous)
__global__ void k_xw(const float* __restrict__ x) {
    __shared__ float sh_x[64 * 129];
    int tid = threadIdx.x;
    int sb0 = blockIdx.x * 64;   // 128 blocks in x
    int cq0 = blockIdx.y * 4;    // 64 blocks in y
    for (int idx = tid; idx < 64 * 128; idx += NTHR) {
        int sl = idx >> 7, i = idx & 127;
        sh_x[sl * 129 + i] = x[(sb0 + sl) * Iq + i];
    }
    __syncthreads();
    int cql = tid >> 6, sl = tid & 63;
    int cq = cq0 + cql;
    float4 acc = make_float4(0.f, 0.f, 0.f, 0.f);
#pragma unroll 4
    for (int i = 0; i < Iq; ++i) {
        float a = sh_x[sl * 129 + i];
        float4 w = __ldg((const float4*)(g_WCx + i * 1024 + cq * 4));
        acc.x = fmaf(a, w.x, acc.x);
        acc.y = fmaf(a, w.y, acc.y);
        acc.z = fmaf(a, w.z, acc.z);
        acc.w = fmaf(a, w.w, acc.w);
    }
    *(float4*)(g_XW + (sb0 + sl) * 1024 + cq * 4) = acc;
}

// ---------------- persistent RNN kernel ----------------

__device__ __forceinline__ void grid_barrier(unsigned target) {
    __threadfence();          // release our stcg writes (per-thread) BEFORE arrival
    __syncthreads();          // all threads' fences done
    if (threadIdx.x == 0) {
        unsigned* p = &g_tickets;
        asm volatile("red.relaxed.gpu.global.add.u32 [%0], %1;" :: "l"(p), "r"(1u) : "memory");
        unsigned v;
        do {
            asm volatile("ld.relaxed.gpu.global.u32 %0, [%1];" : "=r"(v) : "l"(p) : "memory");
        } while (v < target);
    }
    __syncthreads();
}

// stage a 32x512 activation matrix (contiguous in gmem) into padded smem
__device__ __forceinline__ void stage_load(float* sh_in, const float* __restrict__ src) {
    int tid = threadIdx.x;
#pragma unroll
    for (int i = tid; i < Bq * (Hq / 4); i += NTHR) {
        int b = i >> 7, h4 = i & 127;
        float4 v = __ldcg((const float4*)(src + b * Hq + h4 * 4));
        *(float4*)(sh_in + b * SHS + h4 * 4) = v;
    }
}

// compute 32 rows x 8 cols, K=512; weights in SMEM (row stride 8). result in sh_out[32][8].
__device__ __forceinline__ void gemm8s(const float* __restrict__ ws,
                                       const float* __restrict__ bias, int colbase,
                                       const float* sh_in, float* sh_red, float* sh_out) {
    int tid = threadIdx.x;
    int r = tid & 31, kc = (tid >> 5) & 3, q = tid >> 7;  // row, K-chunk, col-quad
    const float* wp = ws + (kc * 128) * 8 + q * 4;        // warp-uniform -> LDS broadcast
    const float* ap = sh_in + r * SHS + kc * 128;
    float4 acc = make_float4(0.f, 0.f, 0.f, 0.f);
#pragma unroll 4
    for (int k = 0; k < 128; k += 4) {
        float4 a  = *(const float4*)(ap + k);
        float4 w0 = *(const float4*)(wp + (k + 0) * 8);
        float4 w1 = *(const float4*)(wp + (k + 1) * 8);
        float4 w2 = *(const float4*)(wp + (k + 2) * 8);
        float4 w3 = *(const float4*)(wp + (k + 3) * 8);
        acc.x = fmaf(a.x, w0.x, acc.x); acc.y = fmaf(a.x, w0.y, acc.y);
        acc.z = fmaf(a.x, w0.z, acc.z); acc.w = fmaf(a.x, w0.w, acc.w);
        acc.x = fmaf(a.y, w1.x, acc.x); acc.y = fmaf(a.y, w1.y, acc.y);
        acc.z = fmaf(a.y, w1.z, acc.z); acc.w = fmaf(a.y, w1.w, acc.w);
        acc.x = fmaf(a.z, w2.x, acc.x); acc.y = fmaf(a.z, w2.y, acc.y);
        acc.z = fmaf(a.z, w2.z, acc.z); acc.w = fmaf(a.z, w2.w, acc.w);
        acc.x = fmaf(a.w, w3.x, acc.x); acc.y = fmaf(a.w, w3.y, acc.y);
        acc.z = fmaf(a.w, w3.z, acc.z); acc.w = fmaf(a.w, w3.w, acc.w);
    }
    ((float4*)sh_red)[(q * 4 + kc) * 32 + r] = acc;
    __syncthreads();
    if (tid < 64) {
        int rr = tid & 31, qq = tid >> 5;
        float4 s0 = ((float4*)sh_red)[(qq * 4 + 0) * 32 + rr];
        float4 s1 = ((float4*)sh_red)[(qq * 4 + 1) * 32 + rr];
        float4 s2 = ((float4*)sh_red)[(qq * 4 + 2) * 32 + rr];
        float4 s3 = ((float4*)sh_red)[(qq * 4 + 3) * 32 + rr];
        float4 bb = __ldg((const float4*)(bias + colbase + qq * 4));
        float4 o;
        o.x = s0.x + s1.x + s2.x + s3.x + bb.x;
        o.y = s0.y + s1.y + s2.y + s3.y + bb.y;
        o.z = s0.z + s1.z + s2.z + s3.z + bb.z;
        o.w = s0.w + s1.w + s2.w + s3.w + bb.w;
        *(float4*)(sh_out + rr * 8 + qq * 4) = o;
    }
    __syncthreads();
}

// sigmoid gates + delay-buffer shift for this CTA's 4 h-cols
__device__ __forceinline__ void buf_update(int cta, const float* sh_in, const float* sh_out) {
    int tid = threadIdx.x;
    if (tid < 128) {
        int b = tid >> 2, hc = tid & 3;
        int col = cta * 4 + hc;
        float ta = sh_out[b * 8 + 2 * hc];
        float me = sh_out[b * 8 + 2 * hc + 1];
        float tau = 16.f / (1.f + expf(-ta));
        tau = fminf(fmaxf(tau, 1.f), 16.f);
        float mem = 1.f / (1.f + expf(-me));
        float hv = sh_in[b * SHS + col];
        int base = b * Hq + col;
#pragma unroll
        for (int d = 0; d < 16; ++d) {
            float nxt = __ldcg(g_dbuf + (d + 1) * (Bq * Hq) + base);
            float w = mem / (1.f + fabsf(tau - (float)(d + 1)));
            __stcg(g_dbuf + d * (Bq * Hq) + base, fmaf(w, hv, nxt));
        }
        __stcg(g_dbuf + 16 * (Bq * Hq) + base, 0.f);
    }
}

__global__ void __launch_bounds__(NTHR, 1) k_rnn(const int* __restrict__ lengths,
                                                 float* __restrict__ out) {
    extern __shared__ float sm[];
    float* sh_in  = sm;                   // 32 * 516 = 16512
    float* sh_red = sh_in + Bq * SHS;     // 1024
    float* sh_out = sh_red + 1024;        // 256
    float* sh_wA  = sh_out + 256;         // 4096 (512 x 8)
    float* sh_wB  = sh_wA + 4096;         // 4096
    float* sh_wD  = sh_wB + 4096;         // 4096
    int tid = threadIdx.x, cta = blockIdx.x;

    // ---- preload this CTA's weight slices into smem (once per launch) ----
#pragma unroll
    for (int i = tid; i < 1024; i += NTHR) {   // float4 index: k = i>>1, half = i&1
        int k = i >> 1, hf = (i & 1) * 4;
        ((float4*)sh_wA)[i] = *(const float4*)(g_WAh + k * 1024 + cta * 8 + hf);
        ((float4*)sh_wB)[i] = *(const float4*)(g_WB  + k * 1024 + cta * 8 + hf);
    }
    if (cta < 72) {
#pragma unroll
        for (int i = tid; i < 1024; i += NTHR) {
            int k = i >> 1, hf = (i & 1) * 4;
            ((float4*)sh_wD)[i] = *(const float4*)(g_WD + k * 576 + cta * 8 + hf);
        }
    }
    int len_b = (tid < 128) ? __ldg(lengths + (tid >> 2)) : 0;
    __syncthreads();

    unsigned nb = 0;

    // ---- encode: 256 steps ----
    for (int t = 0; t < Sq; ++t) {
        // stage A: h0 @ [W_in | W_comb] + XW_t ; combine with mask -> h
        stage_load(sh_in, g_dbuf);  // plane 0 = h0
        __syncthreads();
        gemm8s(sh_wA, g_bA, cta * 8, sh_in, sh_red, sh_out);
        if (tid < 128) {
            int b = tid >> 2, hc = tid & 3;
            int col = cta * 4 + hc;
            float2 xw = *(const float2*)(g_XW + (b * Sq + t) * 1024 + cta * 8 + 2 * hc);
            float h1 = sh_out[b * 8 + 2 * hc]     + xw.x;
            float p  = sh_out[b * 8 + 2 * hc + 1] + xw.y;
            float h = (t < len_b) ? p : h1;
            __stcg(g_hbuf + b * Hq + col, h);
        }
        nb++; grid_barrier(nb * NCTA);
        // stage B: h @ [W_tau | W_mem] -> gates; buffer shift
        stage_load(sh_in, g_hbuf);
        __syncthreads();
        gemm8s(sh_wB, g_bB, cta * 8, sh_in, sh_red, sh_out);
        buf_update(cta, sh_in, sh_out);
        nb++; grid_barrier(nb * NCTA);
    }

    // ---- decode: 64 steps ----
    for (int t = 0; t < OUTL; ++t) {
        if (cta < 72) {   // 72*8 = 576 cols: 512 h cols + 64 out cols
            stage_load(sh_in, g_dbuf);  // plane 0 = h0
            __syncthreads();
            gemm8s(sh_wD, g_bD, cta * 8, sh_in, sh_red, sh_out);
            {
                int b = tid >> 3, j = tid & 7;
                int sc = cta * 8 + j;
                float v = sh_out[b * 8 + j];
                if (sc < Hq) __stcg(g_hbuf + b * Hq + sc, v);
                else          out[b * (OUTL * Cq) + t * Cq + (sc - 512)] = v;
            }
        }
        nb++; grid_barrier(nb * NCTA);
        stage_load(sh_in, g_hbuf);
        __syncthreads();
        gemm8s(sh_wB, g_bB, cta * 8, sh_in, sh_red, sh_out);
        buf_update(cta, sh_in, sh_out);
        nb++; grid_barrier(nb * NCTA);
    }
}

// ---------------- launch ----------------
extern "C" void kernel_launch(void* const* d_in, const int* in_sizes, int n_in,
                              void* d_out, int out_size) {
    const float* x       = (const float*)d_in[0];
    const int*   lengths = (const int*)d_in[1];
    int wi = 2;
    if (n_in >= 13 && in_sizes[2] == 1) wi = 3;  // skip scalar out_lengths if materialized
    const float* W_in   = (const float*)d_in[wi + 0];
    const float* b_in   = (const float*)d_in[wi + 1];
    const float* W_pass = (const float*)d_in[wi + 2];
    const float* b_pass = (const float*)d_in[wi + 3];
    const float* W_tau  = (const float*)d_in[wi + 4];
    const float* b_tau  = (const float*)d_in[wi + 5];
    const float* W_mem  = (const float*)d_in[wi + 6];
    const float* b_mem  = (const float*)d_in[wi + 7];
    const float* W_out  = (const float*)d_in[wi + 8];
    const float* b_out  = (const float*)d_in[wi + 9];
    float* out = (float*)d_out;

    static int smem_set = 0;
    const int smem_bytes = (Bq * SHS + 1024 + 256 + 3 * 4096) * (int)sizeof(float);  // 120320
    if (!smem_set) {
        cudaFuncSetAttribute(k_rnn, cudaFuncAttributeMaxDynamicSharedMemorySize, smem_bytes);
        smem_set = 1;
    }

    k_pre<<<1121, 256>>>(W_in, W_pass, W_tau, W_mem, W_out,
                         b_in, b_pass, b_tau, b_mem, b_out);
    k_xw<<<dim3(128, 64), 256>>>(x);
    k_rnn<<<NCTA, NTHR, smem_bytes>>>(lengths, out);
}

// round 10
// speedup vs baseline: 1.3400x; 1.1253x over previous
#include <cuda_runtime.h>
#include <math.h>

// Problem dims
#define Bq   32
#define Sq   256
#define Iq   128
#define Hq   512
#define Cq   64
#define BUFD 17
#define OUTL 64

#define NCTA 128      // 4 groups x 32 CTAs
#define GCTA 32       // CTAs per group
#define RB   8        // batches per group
#define NTHR 256
#define SHS  516      // padded smem row stride (floats)

// ---------------- device globals ----------------
__device__ __align__(16) float g_WAh[Hq * 1024];      // [W_in | W_in@W_pass], col-interleaved
__device__ __align__(16) float g_WCx[Iq * 1024];      // x-rows, same interleave
__device__ __align__(16) float g_WB [Hq * 1024];      // [W_tau | W_mem] col-interleaved
__device__ __align__(16) float g_WD [Hq * 576];       // decode: 0..511 = W_comb, 512..575 = W_out
__device__ __align__(16) float g_bA [1024];
__device__ __align__(16) float g_bB [1024];
__device__ __align__(16) float g_bD [576];
__device__ __align__(16) float g_XW [Sq * Bq * 1024]; // x @ [Wi_x | Wi_x Wp], [(b*256+t)][1024]
__device__ __align__(16) float g_hbuf[Bq * Hq];
__device__ __align__(16) float g_dbuf[BUFD * Bq * Hq];
__device__ unsigned g_bar[4 * 4 * 64];                // [group][4 sub-counters], 256B apart

// ---------------- fused precompute kernel ----------------
// blocks: [0,320) comb | [320,1344) WB+Wout | 1344 bias | [1345,1361) zero
__global__ void k_pre(const float* __restrict__ W_in, const float* __restrict__ W_pass,
                      const float* __restrict__ W_tau, const float* __restrict__ W_mem,
                      const float* __restrict__ W_out,
                      const float* __restrict__ b_in, const float* __restrict__ b_pass,
                      const float* __restrict__ b_tau, const float* __restrict__ b_mem,
                      const float* __restrict__ b_out) {
    int blk = blockIdx.x, tid = threadIdx.x;
    if (blk < 320) {
        int id = blk * 256 + tid;          // 81920 threads
        int k  = id >> 7;                  // 0..639 (warp-uniform)
        int cq = id & 127;                 // col quad
        float4 acc = make_float4(0.f, 0.f, 0.f, 0.f);
        for (int j = 0; j < Hq; ++j) {
            float a  = __ldg(W_in + k * Hq + j);
            float4 w = __ldg((const float4*)(W_pass + j * Hq + cq * 4));
            acc.x = fmaf(a, w.x, acc.x);
            acc.y = fmaf(a, w.y, acc.y);
            acc.z = fmaf(a, w.z, acc.z);
            acc.w = fmaf(a, w.w, acc.w);
        }
        if (k < Hq) {
            int base = k * 1024;
            float aw[4] = {acc.x, acc.y, acc.z, acc.w};
#pragma unroll
            for (int v = 0; v < 4; ++v) {
                int c = cq * 4 + v;
                g_WAh[base + 2 * c]     = W_in[k * Hq + c];
                g_WAh[base + 2 * c + 1] = aw[v];
            }
            *(float4*)(g_WD + k * 576 + cq * 4) = acc;
        } else {
            int base = (k - Hq) * 1024;
            float aw[4] = {acc.x, acc.y, acc.z, acc.w};
#pragma unroll
            for (int v = 0; v < 4; ++v) {
                int c = cq * 4 + v;
                g_WCx[base + 2 * c]     = W_in[k * Hq + c];
                g_WCx[base + 2 * c + 1] = aw[v];
            }
        }
    } else if (blk < 1344) {
        int id = (blk - 320) * 256 + tid;  // 0..262143
        int k = id >> 9, c = id & 511;
        g_WB[k * 1024 + 2 * c]     = W_tau[k * Hq + c];
        g_WB[k * 1024 + 2 * c + 1] = W_mem[k * Hq + c];
        if (id < Hq * Cq) {
            int k2 = id >> 6, c2 = id & 63;
            g_WD[k2 * 576 + 512 + c2] = W_out[k2 * Cq + c2];
        }
    } else if (blk == 1344) {
#pragma unroll
        for (int hh = 0; hh < 2; ++hh) {
            int c = tid + hh * 256;
            float acc = b_pass[c];
            for (int j = 0; j < Hq; ++j) acc = fmaf(b_in[j], W_pass[j * Hq + c], acc);
            g_bA[2 * c]     = b_in[c];
            g_bA[2 * c + 1] = acc;
            g_bD[c]         = acc;
            g_bB[2 * c]     = b_tau[c];
            g_bB[2 * c + 1] = b_mem[c];
            if (c < Cq) g_bD[512 + c] = b_out[c];
        }
    } else {
        int id = (blk - 1345) * 256 + tid;  // 0..4095
        float4 z = make_float4(0.f, 0.f, 0.f, 0.f);
#pragma unroll
        for (int d = 0; d < BUFD; ++d)
            ((float4*)g_dbuf)[d * 4096 + id] = z;
        if (blk == 1345 && tid < 256)
            ((uint4*)g_bar)[tid] = make_uint4(0u, 0u, 0u, 0u);  // whole g_bar (4KB)
    }
}

// XW[(b*256+t)][col] = sum_i x[b][t][i] * WCx[i][col]
__global__ void k_xw(const float* __restrict__ x) {
    __shared__ float sh_x[64 * 129];
    int tid = threadIdx.x;
    int sb0 = blockIdx.x * 64;
    int cq0 = blockIdx.y * 4;
    for (int idx = tid; idx < 64 * 128; idx += NTHR) {
        int sl = idx >> 7, i = idx & 127;
        sh_x[sl * 129 + i] = x[(sb0 + sl) * Iq + i];
    }
    __syncthreads();
    int cql = tid >> 6, sl = tid & 63;
    int cq = cq0 + cql;
    float4 acc = make_float4(0.f, 0.f, 0.f, 0.f);
#pragma unroll 4
    for (int i = 0; i < Iq; ++i) {
        float a = sh_x[sl * 129 + i];
        float4 w = __ldg((const float4*)(g_WCx + i * 1024 + cq * 4));
        acc.x = fmaf(a, w.x, acc.x);
        acc.y = fmaf(a, w.y, acc.y);
        acc.z = fmaf(a, w.z, acc.z);
        acc.w = fmaf(a, w.w, acc.w);
    }
    *(float4*)(g_XW + (sb0 + sl) * 1024 + cq * 4) = acc;
}

// ---------------- persistent RNN kernel ----------------

// group barrier: 4 sub-counters 256B apart; release-arrive, acquire-poll.
// Light nanosleep backoff after 64 failed polls (fast path untouched).
__device__ __forceinline__ void grid_barrier(unsigned* base, int sub, unsigned target) {
    __syncthreads();
    if (threadIdx.x == 0) {
        asm volatile("red.release.gpu.global.add.u32 [%0], %1;"
                     :: "l"(base + sub * 64), "r"(1u) : "memory");
        unsigned s;
        int spins = 0;
        do {
            unsigned v0, v1, v2, v3;
            asm volatile("ld.acquire.gpu.global.u32 %0, [%1];" : "=r"(v0) : "l"(base +   0) : "memory");
            asm volatile("ld.acquire.gpu.global.u32 %0, [%1];" : "=r"(v1) : "l"(base +  64) : "memory");
            asm volatile("ld.acquire.gpu.global.u32 %0, [%1];" : "=r"(v2) : "l"(base + 128) : "memory");
            asm volatile("ld.acquire.gpu.global.u32 %0, [%1];" : "=r"(v3) : "l"(base + 192) : "memory");
            s = v0 + v1 + v2 + v3;
            if (s >= target) break;
            if (++spins > 64) __nanosleep(32);
        } while (true);
    }
    __syncthreads();
}

// stage RB x 512 activation rows into padded smem (rows = this group's batches)
__device__ __forceinline__ void stage_load(float* sh_in, const float* __restrict__ src) {
    int tid = threadIdx.x;
#pragma unroll
    for (int i = tid; i < RB * (Hq / 4); i += NTHR) {   // 1024 float4
        int b = i >> 7, h4 = i & 127;
        float4 v = __ldcg((const float4*)(src + b * Hq + h4 * 4));
        *(float4*)(sh_in + b * SHS + h4 * 4) = v;
    }
}

// GEMM: RB(8) rows x NC cols, K=512; weights in smem row-stride NC. Out: sh_out[8][NC].
// thread map: r=tid&7, q=(tid>>3)&7 (col quad), kc=tid>>6 (K chunk) — kc warp-uniform.
template<int NC>
__device__ __forceinline__ void gemm(const float* __restrict__ ws,
                                     const float* __restrict__ bias, int colbase,
                                     const float* sh_in, float* sh_red, float* sh_out) {
    constexpr int NQ = NC / 4;
    int tid = threadIdx.x;
    int r = tid & 7, q = (tid >> 3) & 7, kc = tid >> 6;
    if (q < NQ) {
        const float* wp = ws + (kc * 128) * NC + q * 4;
        const float* ap = sh_in + r * SHS + kc * 128;
        float4 acc = make_float4(0.f, 0.f, 0.f, 0.f);
#pragma unroll 4
        for (int k = 0; k < 128; k += 4) {
            float4 a  = *(const float4*)(ap + k);
            float4 w0 = *(const float4*)(wp + (k + 0) * NC);
            float4 w1 = *(const float4*)(wp + (k + 1) * NC);
            float4 w2 = *(const float4*)(wp + (k + 2) * NC);
            float4 w3 = *(const float4*)(wp + (k + 3) * NC);
            acc.x = fmaf(a.x, w0.x, acc.x); acc.y = fmaf(a.x, w0.y, acc.y);
            acc.z = fmaf(a.x, w0.z, acc.z); acc.w = fmaf(a.x, w0.w, acc.w);
            acc.x = fmaf(a.y, w1.x, acc.x); acc.y = fmaf(a.y, w1.y, acc.y);
            acc.z = fmaf(a.y, w1.z, acc.z); acc.w = fmaf(a.y, w1.w, acc.w);
            acc.x = fmaf(a.z, w2.x, acc.x); acc.y = fmaf(a.z, w2.y, acc.y);
            acc.z = fmaf(a.z, w2.z, acc.z); acc.w = fmaf(a.z, w2.w, acc.w);
            acc.x = fmaf(a.w, w3.x, acc.x); acc.y = fmaf(a.w, w3.y, acc.y);
            acc.z = fmaf(a.w, w3.z, acc.z); acc.w = fmaf(a.w, w3.w, acc.w);
        }
        ((float4*)sh_red)[(q * 4 + kc) * 8 + r] = acc;
    }
    __syncthreads();
    if (tid < NQ * 8) {
        int rr = tid & 7, qq = tid >> 3;
        float4 s0 = ((float4*)sh_red)[(qq * 4 + 0) * 8 + rr];
        float4 s1 = ((float4*)sh_red)[(qq * 4 + 1) * 8 + rr];
        float4 s2 = ((float4*)sh_red)[(qq * 4 + 2) * 8 + rr];
        float4 s3 = ((float4*)sh_red)[(qq * 4 + 3) * 8 + rr];
        float4 bb = __ldg((const float4*)(bias + colbase + qq * 4));
        float4 o;
        o.x = s0.x + s1.x + s2.x + s3.x + bb.x;
        o.y = s0.y + s1.y + s2.y + s3.y + bb.y;
        o.z = s0.z + s1.z + s2.z + s3.z + bb.z;
        o.w = s0.w + s1.w + s2.w + s3.w + bb.w;
        *(float4*)(sh_out + rr * NC + qq * 4) = o;
    }
    __syncthreads();
}

// gates + delay-buffer shift: this CTA's 16 h-cols x 8 batches
__device__ __forceinline__ void buf_update(int b0, int hcol0, const float* sh_in,
                                           const float* sh_out) {
    int tid = threadIdx.x;
    if (tid < 128) {
        int b = tid >> 4, hc = tid & 15;
        float ta = sh_out[b * 32 + 2 * hc];
        float me = sh_out[b * 32 + 2 * hc + 1];
        float tau = 16.f / (1.f + expf(-ta));
        tau = fminf(fmaxf(tau, 1.f), 16.f);
        float mem = 1.f / (1.f + expf(-me));
        int col = hcol0 + hc;
        float hv = sh_in[b * SHS + col];
        int base = (b0 + b) * Hq + col;
#pragma unroll
        for (int d = 0; d < 16; ++d) {
            float nxt = __ldcg(g_dbuf + (d + 1) * (Bq * Hq) + base);
            float w = mem / (1.f + fabsf(tau - (float)(d + 1)));
            __stcg(g_dbuf + d * (Bq * Hq) + base, fmaf(w, hv, nxt));
        }
        __stcg(g_dbuf + 16 * (Bq * Hq) + base, 0.f);
    }
}

__global__ void __launch_bounds__(NTHR, 1) k_rnn(const int* __restrict__ lengths,
                                                 float* __restrict__ out) {
    extern __shared__ float sm[];
    float* sh_in  = sm;                   // 8*516      = 4128
    float* sh_red = sh_in + RB * SHS;     // 1024
    float* sh_out = sh_red + 1024;        // 256
    float* sh_wA  = sh_out + 256;         // 512*32 = 16384
    float* sh_wB  = sh_wA + 16384;        // 16384
    int tid = threadIdx.x, cta = blockIdx.x;
    int grp = cta >> 5, cg = cta & 31;
    int b0 = grp * RB;
    int scol0 = cg * 32;        // stored (interleaved) col base, stage A/B
    int hcol0 = cg * 16;        // h col base
    unsigned* bar = g_bar + grp * 256;
    int sub = cg & 3;

    // ---- preload weight slices ----
#pragma unroll
    for (int i = tid; i < 4096; i += NTHR) {  // k = i>>3, quad = i&7
        int k = i >> 3, c4 = (i & 7) * 4;
        ((float4*)sh_wA)[i] = *(const float4*)(g_WAh + k * 1024 + scol0 + c4);
        ((float4*)sh_wB)[i] = *(const float4*)(g_WB  + k * 1024 + scol0 + c4);
    }
    int len_b = (tid < 128) ? __ldg(lengths + b0 + (tid >> 4)) : 0;
    __syncthreads();

    unsigned nb = 0;

    // ---- encode: 256 steps ----
    for (int t = 0; t < Sq; ++t) {
        stage_load(sh_in, g_dbuf + b0 * Hq);            // plane 0 = h0
        float2 xw = make_float2(0.f, 0.f);
        if (tid < 128) {
            int b = tid >> 4, hc = tid & 15;
            xw = *(const float2*)(g_XW + ((b0 + b) * Sq + t) * 1024 + scol0 + 2 * hc);
        }
        __syncthreads();
        gemm<32>(sh_wA, g_bA, scol0, sh_in, sh_red, sh_out);
        if (tid < 128) {
            int b = tid >> 4, hc = tid & 15;
            float h1 = sh_out[b * 32 + 2 * hc]     + xw.x;
            float p  = sh_out[b * 32 + 2 * hc + 1] + xw.y;
            float h = (t < len_b) ? p : h1;
            __stcg(g_hbuf + (b0 + b) * Hq + hcol0 + hc, h);
        }
        nb++; grid_barrier(bar, sub, nb * GCTA);

        stage_load(sh_in, g_hbuf + b0 * Hq);
        __syncthreads();
        gemm<32>(sh_wB, g_bB, scol0, sh_in, sh_red, sh_out);
        buf_update(b0, hcol0, sh_in, sh_out);
        nb++; grid_barrier(bar, sub, nb * GCTA);
    }

    // ---- reload sh_wA with decode weights (24 cols/CTA for cg<24) ----
    int scol0d = cg * 24;
    if (cg < 24) {
        for (int k = tid; k < Hq; k += NTHR) {
#pragma unroll
            for (int j = 0; j < 6; ++j)
                *(float4*)(sh_wA + k * 24 + j * 4) =
                    *(const float4*)(g_WD + k * 576 + scol0d + j * 4);
        }
    }
    __syncthreads();

    // ---- decode: 64 steps ----
    for (int t = 0; t < OUTL; ++t) {
        if (cg < 24) {
            stage_load(sh_in, g_dbuf + b0 * Hq);        // plane 0 = h0
            __syncthreads();
            gemm<24>(sh_wA, g_bD, scol0d, sh_in, sh_red, sh_out);
            {
                int b = tid >> 5, j = tid & 31;
                if (j < 24) {
                    int sc = scol0d + j;
                    float v = sh_out[b * 24 + j];
                    if (sc < Hq) __stcg(g_hbuf + (b0 + b) * Hq + sc, v);
                    else         out[(b0 + b) * (OUTL * Cq) + t * Cq + (sc - Hq)] = v;
                }
            }
            __syncthreads();
        }
        nb++; grid_barrier(bar, sub, nb * GCTA);

        stage_load(sh_in, g_hbuf + b0 * Hq);
        __syncthreads();
        gemm<32>(sh_wB, g_bB, scol0, sh_in, sh_red, sh_out);
        buf_update(b0, hcol0, sh_in, sh_out);
        nb++; grid_barrier(bar, sub, nb * GCTA);
    }
}

// ---------------- launch ----------------
extern "C" void kernel_launch(void* const* d_in, const int* in_sizes, int n_in,
                              void* d_out, int out_size) {
    const float* x       = (const float*)d_in[0];
    const int*   lengths = (const int*)d_in[1];
    int wi = 2;
    if (n_in >= 13 && in_sizes[2] == 1) wi = 3;
    const float* W_in   = (const float*)d_in[wi + 0];
    const float* b_in   = (const float*)d_in[wi + 1];
    const float* W_pass = (const float*)d_in[wi + 2];
    const float* b_pass = (const float*)d_in[wi + 3];
    const float* W_tau  = (const float*)d_in[wi + 4];
    const float* b_tau  = (const float*)d_in[wi + 5];
    const float* W_mem  = (const float*)d_in[wi + 6];
    const float* b_mem  = (const float*)d_in[wi + 7];
    const float* W_out  = (const float*)d_in[wi + 8];
    const float* b_out  = (const float*)d_in[wi + 9];
    float* out = (float*)d_out;

    static int smem_set = 0;
    const int smem_bytes = (RB * SHS + 1024 + 256 + 2 * 16384) * (int)sizeof(float); // 152704
    if (!smem_set) {
        cudaFuncSetAttribute(k_rnn, cudaFuncAttributeMaxDynamicSharedMemorySize, smem_bytes);
        smem_set = 1;
    }

    k_pre<<<1361, 256>>>(W_in, W_pass, W_tau, W_mem, W_out,
                         b_in, b_pass, b_tau, b_mem, b_out);
    k_xw<<<dim3(128, 64), 256>>>(x);
    k_rnn<<<NCTA, NTHR, smem_bytes>>>(lengths, out);
}

// round 11
// speedup vs baseline: 2.0702x; 1.5450x over previous
#include <cuda_runtime.h>
#include <math.h>

// Problem dims
#define Bq   32
#define Sq   256
#define Iq   128
#define Hq   512
#define Cq   64
#define BUFD 17
#define OUTL 64

#define NCTA 128      // 4 groups x 32 CTAs
#define GCTA 32       // CTAs per group
#define RB   8        // batches per group
#define NTHR 256
#define SHS  516      // padded smem row stride (floats)

// ---------------- device globals ----------------
__device__ __align__(16) float g_WAh[Hq * 1024];      // [W_in | W_in@W_pass], col-interleaved
__device__ __align__(16) float g_WCx[Iq * 1024];      // x-rows, same interleave
__device__ __align__(16) float g_WB [Hq * 1024];      // [W_tau | W_mem] col-interleaved
__device__ __align__(16) float g_WD [Hq * 576];       // decode: 0..511 = W_comb, 512..575 = W_out
__device__ __align__(16) float g_bA [1024];
__device__ __align__(16) float g_bB [1024];
__device__ __align__(16) float g_bD [576];
__device__ __align__(16) float g_XW [Sq * Bq * 1024]; // x @ [Wi_x | Wi_x Wp], [(b*256+t)][1024]
__device__ __align__(16) float g_hbuf[Bq * Hq];       // h broadcast (stage A -> B)
__device__ __align__(16) float g_h0  [Bq * Hq];       // plane-0 broadcast (stage B -> next A)
__device__ unsigned g_bar[256];                       // 4 group counters, 256B apart

// ---------------- fused precompute kernel ----------------
// blocks: [0,320) comb | [320,1344) WB+Wout | 1344 bias | [1345,1361) zero h0/bar
__global__ void k_pre(const float* __restrict__ W_in, const float* __restrict__ W_pass,
                      const float* __restrict__ W_tau, const float* __restrict__ W_mem,
                      const float* __restrict__ W_out,
                      const float* __restrict__ b_in, const float* __restrict__ b_pass,
                      const float* __restrict__ b_tau, const float* __restrict__ b_mem,
                      const float* __restrict__ b_out) {
    int blk = blockIdx.x, tid = threadIdx.x;
    if (blk < 320) {
        int id = blk * 256 + tid;          // 81920 threads
        int k  = id >> 7;                  // 0..639 (warp-uniform)
        int cq = id & 127;                 // col quad
        float4 acc = make_float4(0.f, 0.f, 0.f, 0.f);
        for (int j = 0; j < Hq; ++j) {
            float a  = __ldg(W_in + k * Hq + j);
            float4 w = __ldg((const float4*)(W_pass + j * Hq + cq * 4));
            acc.x = fmaf(a, w.x, acc.x);
            acc.y = fmaf(a, w.y, acc.y);
            acc.z = fmaf(a, w.z, acc.z);
            acc.w = fmaf(a, w.w, acc.w);
        }
        float aw[4] = {acc.x, acc.y, acc.z, acc.w};
        if (k < Hq) {
            int base = k * 1024;
#pragma unroll
            for (int v = 0; v < 4; ++v) {
                int c = cq * 4 + v;
                g_WAh[base + 2 * c]     = W_in[k * Hq + c];
                g_WAh[base + 2 * c + 1] = aw[v];
            }
            *(float4*)(g_WD + k * 576 + cq * 4) = acc;
        } else {
            int base = (k - Hq) * 1024;
#pragma unroll
            for (int v = 0; v < 4; ++v) {
                int c = cq * 4 + v;
                g_WCx[base + 2 * c]     = W_in[k * Hq + c];
                g_WCx[base + 2 * c + 1] = aw[v];
            }
        }
    } else if (blk < 1344) {
        int id = (blk - 320) * 256 + tid;  // 0..262143
        int k = id >> 9, c = id & 511;
        g_WB[k * 1024 + 2 * c]     = W_tau[k * Hq + c];
        g_WB[k * 1024 + 2 * c + 1] = W_mem[k * Hq + c];
        if (id < Hq * Cq) {
            int k2 = id >> 6, c2 = id & 63;
            g_WD[k2 * 576 + 512 + c2] = W_out[k2 * Cq + c2];
        }
    } else if (blk == 1344) {
#pragma unroll
        for (int hh = 0; hh < 2; ++hh) {
            int c = tid + hh * 256;
            float acc = b_pass[c];
            for (int j = 0; j < Hq; ++j) acc = fmaf(b_in[j], W_pass[j * Hq + c], acc);
            g_bA[2 * c]     = b_in[c];
            g_bA[2 * c + 1] = acc;
            g_bD[c]         = acc;
            g_bB[2 * c]     = b_tau[c];
            g_bB[2 * c + 1] = b_mem[c];
            if (c < Cq) g_bD[512 + c] = b_out[c];
        }
    } else {
        int id = (blk - 1345) * 256 + tid;  // 0..4095 -> g_h0 (16384 floats)
        ((float4*)g_h0)[id] = make_float4(0.f, 0.f, 0.f, 0.f);
        if (blk == 1345 && tid < 64)
            ((uint4*)g_bar)[tid] = make_uint4(0u, 0u, 0u, 0u);
    }
}

// XW[(b*256+t)][col] = sum_i x[b][t][i] * WCx[i][col]
__global__ void k_xw(const float* __restrict__ x) {
    __shared__ float sh_x[64 * 129];
    int tid = threadIdx.x;
    int sb0 = blockIdx.x * 64;
    int cq0 = blockIdx.y * 4;
    for (int idx = tid; idx < 64 * 128; idx += NTHR) {
        int sl = idx >> 7, i = idx & 127;
        sh_x[sl * 129 + i] = x[(sb0 + sl) * Iq + i];
    }
    __syncthreads();
    int cql = tid >> 6, sl = tid & 63;
    int cq = cq0 + cql;
    float4 acc = make_float4(0.f, 0.f, 0.f, 0.f);
#pragma unroll 4
    for (int i = 0; i < Iq; ++i) {
        float a = sh_x[sl * 129 + i];
        float4 w = __ldg((const float4*)(g_WCx + i * 1024 + cq * 4));
        acc.x = fmaf(a, w.x, acc.x);
        acc.y = fmaf(a, w.y, acc.y);
        acc.z = fmaf(a, w.z, acc.z);
        acc.w = fmaf(a, w.w, acc.w);
    }
    *(float4*)(g_XW + (sb0 + sl) * 1024 + cq * 4) = acc;
}

// ---------------- persistent RNN kernel ----------------

// group barrier: single counter; release-arrive, RELAXED poll, one acquire re-read.
__device__ __forceinline__ void grid_barrier(unsigned* ctr, unsigned target) {
    __syncthreads();
    if (threadIdx.x == 0) {
        asm volatile("red.release.gpu.global.add.u32 [%0], %1;"
                     :: "l"(ctr), "r"(1u) : "memory");
        unsigned v;
        do {
            asm volatile("ld.relaxed.gpu.global.u32 %0, [%1];"
                         : "=r"(v) : "l"(ctr) : "memory");
        } while (v < target);
        asm volatile("ld.acquire.gpu.global.u32 %0, [%1];"
                     : "=r"(v) : "l"(ctr) : "memory");
    }
    __syncthreads();
}

// stage RB x 512 activation rows into padded smem
__device__ __forceinline__ void stage_load(float* sh_in, const float* __restrict__ src) {
    int tid = threadIdx.x;
#pragma unroll
    for (int i = tid; i < RB * (Hq / 4); i += NTHR) {   // 1024 float4
        int b = i >> 7, h4 = i & 127;
        float4 v = __ldcg((const float4*)(src + b * Hq + h4 * 4));
        *(float4*)(sh_in + b * SHS + h4 * 4) = v;
    }
}

// GEMM: 8 rows x NC cols, K=512; weights in smem row-stride NC; bias in smem (sliced).
template<int NC>
__device__ __forceinline__ void gemm(const float* __restrict__ ws,
                                     const float* __restrict__ bias,
                                     const float* sh_in, float* sh_red, float* sh_out) {
    constexpr int NQ = NC / 4;
    int tid = threadIdx.x;
    int r = tid & 7, q = (tid >> 3) & 7, kc = tid >> 6;
    if (q < NQ) {
        const float* wp = ws + (kc * 128) * NC + q * 4;
        const float* ap = sh_in + r * SHS + kc * 128;
        float4 acc = make_float4(0.f, 0.f, 0.f, 0.f);
#pragma unroll 4
        for (int k = 0; k < 128; k += 4) {
            float4 a  = *(const float4*)(ap + k);
            float4 w0 = *(const float4*)(wp + (k + 0) * NC);
            float4 w1 = *(const float4*)(wp + (k + 1) * NC);
            float4 w2 = *(const float4*)(wp + (k + 2) * NC);
            float4 w3 = *(const float4*)(wp + (k + 3) * NC);
            acc.x = fmaf(a.x, w0.x, acc.x); acc.y = fmaf(a.x, w0.y, acc.y);
            acc.z = fmaf(a.x, w0.z, acc.z); acc.w = fmaf(a.x, w0.w, acc.w);
            acc.x = fmaf(a.y, w1.x, acc.x); acc.y = fmaf(a.y, w1.y, acc.y);
            acc.z = fmaf(a.y, w1.z, acc.z); acc.w = fmaf(a.y, w1.w, acc.w);
            acc.x = fmaf(a.z, w2.x, acc.x); acc.y = fmaf(a.z, w2.y, acc.y);
            acc.z = fmaf(a.z, w2.z, acc.z); acc.w = fmaf(a.z, w2.w, acc.w);
            acc.x = fmaf(a.w, w3.x, acc.x); acc.y = fmaf(a.w, w3.y, acc.y);
            acc.z = fmaf(a.w, w3.z, acc.z); acc.w = fmaf(a.w, w3.w, acc.w);
        }
        ((float4*)sh_red)[(q * 4 + kc) * 8 + r] = acc;
    }
    __syncthreads();
    if (tid < NQ * 8) {
        int rr = tid & 7, qq = tid >> 3;
        float4 s0 = ((float4*)sh_red)[(qq * 4 + 0) * 8 + rr];
        float4 s1 = ((float4*)sh_red)[(qq * 4 + 1) * 8 + rr];
        float4 s2 = ((float4*)sh_red)[(qq * 4 + 2) * 8 + rr];
        float4 s3 = ((float4*)sh_red)[(qq * 4 + 3) * 8 + rr];
        float4 bb = *(const float4*)(bias + qq * 4);
        float4 o;
        o.x = s0.x + s1.x + s2.x + s3.x + bb.x;
        o.y = s0.y + s1.y + s2.y + s3.y + bb.y;
        o.z = s0.z + s1.z + s2.z + s3.z + bb.z;
        o.w = s0.w + s1.w + s2.w + s3.w + bb.w;
        *(float4*)(sh_out + rr * NC + qq * 4) = o;
    }
    __syncthreads();
}

__global__ void __launch_bounds__(NTHR, 1) k_rnn(const int* __restrict__ lengths,
                                                 float* __restrict__ out) {
    extern __shared__ float sm[];
    float* sh_in   = sm;                    // 4128
    float* sh_red  = sh_in + RB * SHS;      // 1024
    float* sh_out  = sh_red + 1024;         // 256
    float* sh_bias = sh_out + 256;          // 96 (bA 32 | bB 32 | bD 32)
    float* sh_db   = sh_bias + 96;          // 128*17 = 2176 (delay buffer slices)
    float* sh_wA   = sh_db + 2176;          // 16384
    float* sh_wB   = sh_wA + 16384;         // 16384
    int tid = threadIdx.x, cta = blockIdx.x;
    int grp = cta >> 5, cg = cta & 31;
    int b0 = grp * RB;
    int scol0 = cg * 32;        // interleaved col base (stages A/B)
    int hcol0 = cg * 16;        // h col base
    unsigned* bar = g_bar + grp * 64;

    // ---- preload weight slices + biases; zero local delay buffer ----
#pragma unroll
    for (int i = tid; i < 4096; i += NTHR) {
        int k = i >> 3, c4 = (i & 7) * 4;
        ((float4*)sh_wA)[i] = *(const float4*)(g_WAh + k * 1024 + scol0 + c4);
        ((float4*)sh_wB)[i] = *(const float4*)(g_WB  + k * 1024 + scol0 + c4);
    }
    if (tid < 32) {
        sh_bias[tid]      = g_bA[scol0 + tid];
        sh_bias[32 + tid] = g_bB[scol0 + tid];
        if (cg < 24 && tid < 24) sh_bias[64 + tid] = g_bD[cg * 24 + tid];
    }
    for (int i = tid; i < 128 * BUFD; i += NTHR) sh_db[i] = 0.f;
    int len_b = (tid < 128) ? __ldg(lengths + b0 + (tid >> 4)) : 0;
    __syncthreads();

    unsigned nb = 0;

    // ---- encode: 256 steps ----
    for (int t = 0; t < Sq; ++t) {
        // stage A: h0 @ [W_in | W_comb] + XW_t -> h
        stage_load(sh_in, g_h0 + b0 * Hq);
        float2 xw = make_float2(0.f, 0.f);
        if (tid < 128) {
            int b = tid >> 4, hc = tid & 15;
            xw = *(const float2*)(g_XW + ((b0 + b) * Sq + t) * 1024 + scol0 + 2 * hc);
        }
        __syncthreads();
        gemm<32>(sh_wA, sh_bias, sh_in, sh_red, sh_out);
        if (tid < 128) {
            int b = tid >> 4, hc = tid & 15;
            float h1 = sh_out[b * 32 + 2 * hc]     + xw.x;
            float p  = sh_out[b * 32 + 2 * hc + 1] + xw.y;
            float h = (t < len_b) ? p : h1;
            __stcg(g_hbuf + (b0 + b) * Hq + hcol0 + hc, h);
        }
        nb++; grid_barrier(bar, nb * GCTA);

        // stage B: h @ [W_tau | W_mem] -> gates; smem delay-buffer shift; publish plane 0
        stage_load(sh_in, g_hbuf + b0 * Hq);
        __syncthreads();
        gemm<32>(sh_wB, sh_bias + 32, sh_in, sh_red, sh_out);
        if (tid < 128) {
            int b = tid >> 4, hc = tid & 15;
            float ta = sh_out[b * 32 + 2 * hc];
            float me = sh_out[b * 32 + 2 * hc + 1];
            float tau = __fdividef(16.f, 1.f + __expf(-ta));
            tau = fminf(fmaxf(tau, 1.f), 16.f);
            float mem = __fdividef(1.f, 1.f + __expf(-me));
            float hv = sh_in[b * SHS + hcol0 + hc];
            float* dp = sh_db + tid * BUFD;
#pragma unroll
            for (int d = 0; d < 16; ++d) {
                float w = __fdividef(mem, 1.f + fabsf(tau - (float)(d + 1)));
                dp[d] = fmaf(w, hv, dp[d + 1]);
            }
            dp[16] = 0.f;
            __stcg(g_h0 + (b0 + b) * Hq + hcol0 + hc, dp[0]);
        }
        nb++; grid_barrier(bar, nb * GCTA);
    }

    // ---- reload sh_wA with decode weights (24 cols/CTA for cg<24) ----
    int scol0d = cg * 24;
    if (cg < 24) {
        for (int k = tid; k < Hq; k += NTHR) {
#pragma unroll
            for (int j = 0; j < 6; ++j)
                *(float4*)(sh_wA + k * 24 + j * 4) =
                    *(const float4*)(g_WD + k * 576 + scol0d + j * 4);
        }
    }
    __syncthreads();

    // ---- decode: 64 steps ----
    for (int t = 0; t < OUTL; ++t) {
        if (cg < 24) {
            stage_load(sh_in, g_h0 + b0 * Hq);
            __syncthreads();
            gemm<24>(sh_wA, sh_bias + 64, sh_in, sh_red, sh_out);
            {
                int b = tid >> 5, j = tid & 31;
                if (j < 24) {
                    int sc = scol0d + j;
                    float v = sh_out[b * 24 + j];
                    if (sc < Hq) __stcg(g_hbuf + (b0 + b) * Hq + sc, v);
                    else         out[(b0 + b) * (OUTL * Cq) + t * Cq + (sc - Hq)] = v;
                }
            }
            __syncthreads();
        }
        nb++; grid_barrier(bar, nb * GCTA);

        stage_load(sh_in, g_hbuf + b0 * Hq);
        __syncthreads();
        gemm<32>(sh_wB, sh_bias + 32, sh_in, sh_red, sh_out);
        if (tid < 128) {
            int b = tid >> 4, hc = tid & 15;
            float ta = sh_out[b * 32 + 2 * hc];
            float me = sh_out[b * 32 + 2 * hc + 1];
            float tau = __fdividef(16.f, 1.f + __expf(-ta));
            tau = fminf(fmaxf(tau, 1.f), 16.f);
            float mem = __fdividef(1.f, 1.f + __expf(-me));
            float hv = sh_in[b * SHS + hcol0 + hc];
            float* dp = sh_db + tid * BUFD;
#pragma unroll
            for (int d = 0; d < 16; ++d) {
                float w = __fdividef(mem, 1.f + fabsf(tau - (float)(d + 1)));
                dp[d] = fmaf(w, hv, dp[d + 1]);
            }
            dp[16] = 0.f;
            __stcg(g_h0 + (b0 + b) * Hq + hcol0 + hc, dp[0]);
        }
        nb++; grid_barrier(bar, nb * GCTA);
    }
}

// ---------------- launch ----------------
extern "C" void kernel_launch(void* const* d_in, const int* in_sizes, int n_in,
                              void* d_out, int out_size) {
    const float* x       = (const float*)d_in[0];
    const int*   lengths = (const int*)d_in[1];
    int wi = 2;
    if (n_in >= 13 && in_sizes[2] == 1) wi = 3;
    const float* W_in   = (const float*)d_in[wi + 0];
    const float* b_in   = (const float*)d_in[wi + 1];
    const float* W_pass = (const float*)d_in[wi + 2];
    const float* b_pass = (const float*)d_in[wi + 3];
    const float* W_tau  = (const float*)d_in[wi + 4];
    const float* b_tau  = (const float*)d_in[wi + 5];
    const float* W_mem  = (const float*)d_in[wi + 6];
    const float* b_mem  = (const float*)d_in[wi + 7];
    const float* W_out  = (const float*)d_in[wi + 8];
    const float* b_out  = (const float*)d_in[wi + 9];
    float* out = (float*)d_out;

    static int smem_set = 0;
    const int smem_bytes = (RB * SHS + 1024 + 256 + 96 + 128 * BUFD + 2 * 16384)
                           * (int)sizeof(float);   // 161792
    if (!smem_set) {
        cudaFuncSetAttribute(k_rnn, cudaFuncAttributeMaxDynamicSharedMemorySize, smem_bytes);
        smem_set = 1;
    }

    k_pre<<<1361, 256>>>(W_in, W_pass, W_tau, W_mem, W_out,
                         b_in, b_pass, b_tau, b_mem, b_out);
    k_xw<<<dim3(128, 64), 256>>>(x);
    k_rnn<<<NCTA, NTHR, smem_bytes>>>(lengths, out);
}